// round 3
// baseline (speedup 1.0000x reference)
#include <cuda_runtime.h>
#include <math.h>

// Problem constants
#define BB 2
#define SS 2048
#define EE 1024
#define HH 16
#define DH 64
#define M_TOK (BB * SS)        // 4096
#define N_QKV (3 * EE)         // 3072

// Scratch (__device__ globals; no allocations allowed)
__device__ float g_q[M_TOK * EE];      // Q only [4096, 1024]
__device__ float g_ctx[M_TOK * EE];

// ---------------------------------------------------------------------------
// helpers
// ---------------------------------------------------------------------------
__device__ __forceinline__ unsigned f2tf(float x) {
    unsigned r;
    asm("cvt.rna.tf32.f32 %0, %1;" : "=r"(r) : "f"(x));
    return r;
}

__device__ __forceinline__ void mma_tf32(float c[4], const unsigned a[4], const unsigned b[2]) {
    asm volatile(
        "mma.sync.aligned.m16n8k8.row.col.f32.tf32.tf32.f32 "
        "{%0,%1,%2,%3}, {%4,%5,%6,%7}, {%8,%9}, {%0,%1,%2,%3};"
        : "+f"(c[0]), "+f"(c[1]), "+f"(c[2]), "+f"(c[3])
        : "r"(a[0]), "r"(a[1]), "r"(a[2]), "r"(a[3]), "r"(b[0]), "r"(b[1]));
}

// ---------------------------------------------------------------------------
// TF32 GEMM: C = A @ B + bias.  128x128 tile, BK=16, 256 threads.
// If SPLIT3: N==3072 and output columns are routed per 1024-segment to
// C0 (q scratch), C1 (key cache), C2 (value cache), each ldc=1024.
// ---------------------------------------------------------------------------
#define GBM 128
#define GBN 128
#define GBK 16
#define GAS (GBK + 4)
#define GBS (GBN + 8)

template<bool SPLIT3>
__global__ __launch_bounds__(256)
void gemm_tf32_kernel(const float* __restrict__ A,
                      const float* __restrict__ B,
                      const float* __restrict__ bias,
                      float* __restrict__ C0,
                      float* __restrict__ C1,
                      float* __restrict__ C2,
                      int M, int N, int K)
{
    __shared__ float As[GBM * GAS];
    __shared__ float Bs[GBK * GBS];

    const int tid  = threadIdx.x;
    const int warp = tid >> 5;
    const int lane = tid & 31;
    const int g    = lane >> 2;
    const int tg   = lane & 3;
    const int row0 = blockIdx.y * GBM;
    const int col0 = blockIdx.x * GBN;
    const int wm   = (warp >> 1) * 32;
    const int wn   = (warp & 1) * 64;

    const int a_r0 = tid >> 2, a_c4 = (tid & 3) * 4;
    const int b_r0 = tid >> 5, b_c4 = (tid & 31) * 4;

    float4 pa0, pa1, pb0, pb1;
    pa0 = *(const float4*)&A[(size_t)(row0 + a_r0) * K + a_c4];
    pa1 = *(const float4*)&A[(size_t)(row0 + a_r0 + 64) * K + a_c4];
    pb0 = *(const float4*)&B[(size_t)(b_r0) * N + col0 + b_c4];
    pb1 = *(const float4*)&B[(size_t)(b_r0 + 8) * N + col0 + b_c4];

    float acc[2][8][4];
#pragma unroll
    for (int mt = 0; mt < 2; mt++)
#pragma unroll
        for (int nt = 0; nt < 8; nt++)
#pragma unroll
            for (int i = 0; i < 4; i++) acc[mt][nt][i] = 0.0f;

    const int ksteps = K / GBK;
    for (int kt = 0; kt < ksteps; kt++) {
        {
            unsigned* sa = (unsigned*)As;
            unsigned* sb = (unsigned*)Bs;
            *(uint4*)&sa[a_r0 * GAS + a_c4] =
                make_uint4(f2tf(pa0.x), f2tf(pa0.y), f2tf(pa0.z), f2tf(pa0.w));
            *(uint4*)&sa[(a_r0 + 64) * GAS + a_c4] =
                make_uint4(f2tf(pa1.x), f2tf(pa1.y), f2tf(pa1.z), f2tf(pa1.w));
            *(uint4*)&sb[b_r0 * GBS + b_c4] =
                make_uint4(f2tf(pb0.x), f2tf(pb0.y), f2tf(pb0.z), f2tf(pb0.w));
            *(uint4*)&sb[(b_r0 + 8) * GBS + b_c4] =
                make_uint4(f2tf(pb1.x), f2tf(pb1.y), f2tf(pb1.z), f2tf(pb1.w));
        }
        __syncthreads();

        if (kt + 1 < ksteps) {
            const int k0 = (kt + 1) * GBK;
            pa0 = *(const float4*)&A[(size_t)(row0 + a_r0) * K + k0 + a_c4];
            pa1 = *(const float4*)&A[(size_t)(row0 + a_r0 + 64) * K + k0 + a_c4];
            pb0 = *(const float4*)&B[(size_t)(k0 + b_r0) * N + col0 + b_c4];
            pb1 = *(const float4*)&B[(size_t)(k0 + b_r0 + 8) * N + col0 + b_c4];
        }

        const unsigned* sa = (const unsigned*)As;
        const unsigned* sb = (const unsigned*)Bs;
#pragma unroll
        for (int ks = 0; ks < 2; ks++) {
            unsigned af[2][4];
#pragma unroll
            for (int mt = 0; mt < 2; mt++) {
                const int r = wm + mt * 16 + g;
                af[mt][0] = sa[r * GAS + ks * 8 + tg];
                af[mt][1] = sa[(r + 8) * GAS + ks * 8 + tg];
                af[mt][2] = sa[r * GAS + ks * 8 + tg + 4];
                af[mt][3] = sa[(r + 8) * GAS + ks * 8 + tg + 4];
            }
#pragma unroll
            for (int nt = 0; nt < 8; nt++) {
                unsigned bf[2];
                bf[0] = sb[(ks * 8 + tg) * GBS + wn + nt * 8 + g];
                bf[1] = sb[(ks * 8 + tg + 4) * GBS + wn + nt * 8 + g];
#pragma unroll
                for (int mt = 0; mt < 2; mt++)
                    mma_tf32(acc[mt][nt], af[mt], bf);
            }
        }
        __syncthreads();
    }

    // epilogue with optional 3-way column routing (col0 is 128-aligned,
    // segments are 1024-wide -> whole block maps to one segment)
    float* Cout;
    int    ccol0, ldc;
    if (SPLIT3) {
        ldc = EE;
        if (col0 < EE)            { Cout = C0; ccol0 = col0; }
        else if (col0 < 2 * EE)   { Cout = C1; ccol0 = col0 - EE; }
        else                      { Cout = C2; ccol0 = col0 - 2 * EE; }
    } else {
        Cout = C0; ccol0 = col0; ldc = N;
    }

#pragma unroll
    for (int mt = 0; mt < 2; mt++) {
        const int r0 = row0 + wm + mt * 16 + g;
#pragma unroll
        for (int nt = 0; nt < 8; nt++) {
            const int cg = col0 + wn + nt * 8 + 2 * tg;     // bias index
            const int c  = ccol0 + wn + nt * 8 + 2 * tg;    // store index
            float2 bz = *(const float2*)&bias[cg];
            *(float2*)&Cout[(size_t)r0 * ldc + c] =
                make_float2(acc[mt][nt][0] + bz.x, acc[mt][nt][1] + bz.y);
            *(float2*)&Cout[(size_t)(r0 + 8) * ldc + c] =
                make_float2(acc[mt][nt][2] + bz.x, acc[mt][nt][3] + bz.y);
        }
    }
}

// ---------------------------------------------------------------------------
// Flash attention, tf32 mma. 256 threads (8 warps), q-tile 128, k-tile 64.
// Each warp owns 16 q rows. K/V read from the cache outputs (ld 1024).
// smem: K[64][68] | V[64][72] | PQ[128][68]  (~69KB)
// ---------------------------------------------------------------------------
#define AK_STR 68
#define AV_STR 72
#define AP_STR 68
#define SM_K 0
#define SM_V (SM_K + 64 * AK_STR)
#define SM_P (SM_V + 64 * AV_STR)
#define ATTN_SMEM_FLOATS (SM_P + 128 * AP_STR)

__global__ __launch_bounds__(256, 2)
void flash_attn_tf32_kernel(const float* __restrict__ qsrc,
                            const float* __restrict__ ksrc,
                            const float* __restrict__ vsrc,
                            const float* __restrict__ bias,
                            float* __restrict__ ctx)
{
    extern __shared__ float sm[];
    unsigned* smu = (unsigned*)sm;

    const int qb   = gridDim.x - 1 - blockIdx.x;   // largest tiles first
    const int h    = blockIdx.y;
    const int b    = blockIdx.z;
    const int tid  = threadIdx.x;
    const int warp = tid >> 5;
    const int lane = tid & 31;
    const int g    = lane >> 2;
    const int tg   = lane & 3;
    const int w16  = warp * 16;

    const int tok0 = b * SS;                 // token base for this batch
    const float scale = 0.125f;              // 1/sqrt(64)

    // stage Q tile (128 x 64) scaled+tf32 into the P region
#pragma unroll
    for (int i = 0; i < 8; i++) {
        int f = tid + i * 256;               // f4 index over 128x16
        int r = f >> 4, c4 = (f & 15) * 4;
        float4 q = *(const float4*)&qsrc[(size_t)(tok0 + qb * 128 + r) * EE + h * DH + c4];
        *(uint4*)&smu[SM_P + r * AP_STR + c4] =
            make_uint4(f2tf(q.x * scale), f2tf(q.y * scale),
                       f2tf(q.z * scale), f2tf(q.w * scale));
    }
    __syncthreads();

    // Q fragments resident in registers
    unsigned qa[8][4];
#pragma unroll
    for (int ks = 0; ks < 8; ks++) {
        const int r = w16 + g;
        qa[ks][0] = smu[SM_P + r * AP_STR + ks * 8 + tg];
        qa[ks][1] = smu[SM_P + (r + 8) * AP_STR + ks * 8 + tg];
        qa[ks][2] = smu[SM_P + r * AP_STR + ks * 8 + tg + 4];
        qa[ks][3] = smu[SM_P + (r + 8) * AP_STR + ks * 8 + tg + 4];
    }

    float m0 = -1e30f, m1 = -1e30f, l0 = 0.0f, l1 = 0.0f;
    float out[8][4];
#pragma unroll
    for (int nt = 0; nt < 8; nt++)
#pragma unroll
        for (int i = 0; i < 4; i++) out[nt][i] = 0.0f;

    const int qg0 = qb * 128 + w16 + g;      // global q row (in-sequence)
    const int qg1 = qg0 + 8;
    const int nkb = 2 * qb + 2;              // k tiles covering causal span

    for (int kb = 0; kb < nkb; kb++) {
        __syncthreads();
        // stage K and V tiles (64 x 64)
#pragma unroll
        for (int i = 0; i < 4; i++) {
            int f = tid + i * 256;
            int r = f >> 4, c4 = (f & 15) * 4;
            size_t gidx = (size_t)(tok0 + kb * 64 + r) * EE + h * DH + c4;
            float4 k = *(const float4*)&ksrc[gidx];
            float4 v = *(const float4*)&vsrc[gidx];
            *(uint4*)&smu[SM_K + r * AK_STR + c4] =
                make_uint4(f2tf(k.x), f2tf(k.y), f2tf(k.z), f2tf(k.w));
            *(uint4*)&smu[SM_V + r * AV_STR + c4] =
                make_uint4(f2tf(v.x), f2tf(v.y), f2tf(v.z), f2tf(v.w));
        }
        __syncthreads();

        // S = Q K^T (16x64 per warp)
        float s[8][4];
#pragma unroll
        for (int nt = 0; nt < 8; nt++) {
#pragma unroll
            for (int i = 0; i < 4; i++) s[nt][i] = 0.0f;
#pragma unroll
            for (int ks = 0; ks < 8; ks++) {
                unsigned bf[2];
                bf[0] = smu[SM_K + (nt * 8 + g) * AK_STR + ks * 8 + tg];
                bf[1] = smu[SM_K + (nt * 8 + g) * AK_STR + ks * 8 + tg + 4];
                mma_tf32(s[nt], qa[ks], bf);
            }
        }

        // bias + causal mask
        const bool need_mask = (kb * 64 + 63) > qg0;   // also covers qg1 rows sep.
#pragma unroll
        for (int nt = 0; nt < 8; nt++) {
            const int kg = kb * 64 + nt * 8 + 2 * tg;
            float2 bz0 = *(const float2*)&bias[(size_t)qg0 * SS + kg];
            float2 bz1 = *(const float2*)&bias[(size_t)qg1 * SS + kg];
            s[nt][0] += bz0.x; s[nt][1] += bz0.y;
            s[nt][2] += bz1.x; s[nt][3] += bz1.y;
            if (need_mask) {
                if (kg     > qg0) s[nt][0] = -1e9f;
                if (kg + 1 > qg0) s[nt][1] = -1e9f;
                if (kg     > qg1) s[nt][2] = -1e9f;
                if (kg + 1 > qg1) s[nt][3] = -1e9f;
            }
        }

        // online softmax
        float mx0 = -1e30f, mx1 = -1e30f;
#pragma unroll
        for (int nt = 0; nt < 8; nt++) {
            mx0 = fmaxf(mx0, fmaxf(s[nt][0], s[nt][1]));
            mx1 = fmaxf(mx1, fmaxf(s[nt][2], s[nt][3]));
        }
        mx0 = fmaxf(mx0, __shfl_xor_sync(0xffffffffu, mx0, 1));
        mx0 = fmaxf(mx0, __shfl_xor_sync(0xffffffffu, mx0, 2));
        mx1 = fmaxf(mx1, __shfl_xor_sync(0xffffffffu, mx1, 1));
        mx1 = fmaxf(mx1, __shfl_xor_sync(0xffffffffu, mx1, 2));
        float mn0 = fmaxf(m0, mx0), mn1 = fmaxf(m1, mx1);
        float c0 = __expf(m0 - mn0), c1 = __expf(m1 - mn1);
        m0 = mn0; m1 = mn1;

        float rs0 = 0.0f, rs1 = 0.0f;
#pragma unroll
        for (int nt = 0; nt < 8; nt++) {
            s[nt][0] = __expf(s[nt][0] - mn0);
            s[nt][1] = __expf(s[nt][1] - mn0);
            s[nt][2] = __expf(s[nt][2] - mn1);
            s[nt][3] = __expf(s[nt][3] - mn1);
            rs0 += s[nt][0] + s[nt][1];
            rs1 += s[nt][2] + s[nt][3];
        }
        rs0 += __shfl_xor_sync(0xffffffffu, rs0, 1);
        rs0 += __shfl_xor_sync(0xffffffffu, rs0, 2);
        rs1 += __shfl_xor_sync(0xffffffffu, rs1, 1);
        rs1 += __shfl_xor_sync(0xffffffffu, rs1, 2);
        l0 = l0 * c0 + rs0;
        l1 = l1 * c1 + rs1;
#pragma unroll
        for (int nt = 0; nt < 8; nt++) {
            out[nt][0] *= c0; out[nt][1] *= c0;
            out[nt][2] *= c1; out[nt][3] *= c1;
        }

        // P -> smem (warp-private rows)
#pragma unroll
        for (int nt = 0; nt < 8; nt++) {
            *(uint2*)&smu[SM_P + (w16 + g) * AP_STR + nt * 8 + 2 * tg] =
                make_uint2(f2tf(s[nt][0]), f2tf(s[nt][1]));
            *(uint2*)&smu[SM_P + (w16 + g + 8) * AP_STR + nt * 8 + 2 * tg] =
                make_uint2(f2tf(s[nt][2]), f2tf(s[nt][3]));
        }
        __syncwarp();

        // out += P V
#pragma unroll
        for (int ks = 0; ks < 8; ks++) {
            unsigned pa[4];
            pa[0] = smu[SM_P + (w16 + g) * AP_STR + ks * 8 + tg];
            pa[1] = smu[SM_P + (w16 + g + 8) * AP_STR + ks * 8 + tg];
            pa[2] = smu[SM_P + (w16 + g) * AP_STR + ks * 8 + tg + 4];
            pa[3] = smu[SM_P + (w16 + g + 8) * AP_STR + ks * 8 + tg + 4];
#pragma unroll
            for (int nt = 0; nt < 8; nt++) {
                unsigned vf[2];
                vf[0] = smu[SM_V + (ks * 8 + tg) * AV_STR + nt * 8 + g];
                vf[1] = smu[SM_V + (ks * 8 + tg + 4) * AV_STR + nt * 8 + g];
                mma_tf32(out[nt], pa, vf);
            }
        }
    }

    // write ctx
    const float il0 = 1.0f / l0, il1 = 1.0f / l1;
    const int trow = tok0 + qb * 128 + w16 + g;
#pragma unroll
    for (int nt = 0; nt < 8; nt++) {
        const int c = h * DH + nt * 8 + 2 * tg;
        *(float2*)&ctx[(size_t)trow * EE + c] =
            make_float2(out[nt][0] * il0, out[nt][1] * il0);
        *(float2*)&ctx[(size_t)(trow + 8) * EE + c] =
            make_float2(out[nt][2] * il1, out[nt][3] * il1);
    }
}

// ---------------------------------------------------------------------------
// kernel_launch
// ---------------------------------------------------------------------------
extern "C" void kernel_launch(void* const* d_in, const int* in_sizes, int n_in,
                              void* d_out, int out_size)
{
    const float* hidden = (const float*)d_in[0];
    const float* bias   = (const float*)d_in[1];
    const float* Wqkv   = (const float*)d_in[2];
    const float* bqkv   = (const float*)d_in[3];
    const float* Wproj  = (const float*)d_in[4];
    const float* bproj  = (const float*)d_in[5];
    float* out = (float*)d_out;

    float* qbuf;
    float* ctx;
    cudaGetSymbolAddress((void**)&qbuf, g_q);
    cudaGetSymbolAddress((void**)&ctx, g_ctx);

    float* out_attn = out;
    float* out_key  = out + (size_t)M_TOK * EE;
    float* out_val  = out + (size_t)2 * M_TOK * EE;

    static const int attn_smem = ATTN_SMEM_FLOATS * 4;   // ~69 KB
    cudaFuncSetAttribute(flash_attn_tf32_kernel,
                         cudaFuncAttributeMaxDynamicSharedMemorySize, attn_smem);

    // 1) QKV GEMM with fused cache split: q->qbuf, k->out_key, v->out_val
    {
        dim3 grid(N_QKV / GBN, M_TOK / GBM);
        gemm_tf32_kernel<true><<<grid, 256>>>(hidden, Wqkv, bqkv,
                                              qbuf, out_key, out_val,
                                              M_TOK, N_QKV, EE);
    }
    // 2) attention
    {
        dim3 grid(SS / 128, HH, BB);
        flash_attn_tf32_kernel<<<grid, 256, attn_smem>>>(qbuf, out_key, out_val,
                                                         bias, ctx);
    }
    // 3) projection
    {
        dim3 grid(EE / GBN, M_TOK / GBM);
        gemm_tf32_kernel<false><<<grid, 256>>>(ctx, Wproj, bproj,
                                               out_attn, nullptr, nullptr,
                                               M_TOK, EE, EE);
    }
}

// round 5
// speedup vs baseline: 1.1152x; 1.1152x over previous
#include <cuda_runtime.h>
#include <stdint.h>
#include <math.h>

// Problem constants
#define BB 2
#define SS 2048
#define EE 1024
#define HH 16
#define DH 64
#define M_TOK (BB * SS)        // 4096
#define N_QKV (3 * EE)         // 3072

// Scratch (__device__ globals; no allocations allowed)
__device__ float g_q[M_TOK * EE];        // Q pre-scaled + tf32-rounded
__device__ float g_ctx[M_TOK * EE];      // attention output (tf32-rounded)
__device__ float g_a[M_TOK * EE];        // rounded hidden states
__device__ float g_wqkv_t[N_QKV * EE];   // Wqkv^T rounded [3072,1024]
__device__ float g_wproj_t[EE * EE];     // Wproj^T rounded [1024,1024]

// ---------------------------------------------------------------------------
// helpers
// ---------------------------------------------------------------------------
__device__ __forceinline__ unsigned f2tf(float x) {
    unsigned r;
    asm("cvt.rna.tf32.f32 %0, %1;" : "=r"(r) : "f"(x));
    return r;
}
__device__ __forceinline__ float f2tf_f(float x) { return __uint_as_float(f2tf(x)); }

__device__ __forceinline__ void mma_tf32(float c[4], const unsigned a[4], const unsigned b[2]) {
    asm volatile(
        "mma.sync.aligned.m16n8k8.row.col.f32.tf32.tf32.f32 "
        "{%0,%1,%2,%3}, {%4,%5,%6,%7}, {%8,%9}, {%0,%1,%2,%3};"
        : "+f"(c[0]), "+f"(c[1]), "+f"(c[2]), "+f"(c[3])
        : "r"(a[0]), "r"(a[1]), "r"(a[2]), "r"(a[3]), "r"(b[0]), "r"(b[1]));
}

__device__ __forceinline__ uint32_t smem_u32(const void* p) {
    uint32_t a;
    asm("{ .reg .u64 t; cvta.to.shared.u64 t, %1; cvt.u32.u64 %0, t; }"
        : "=r"(a) : "l"(p));
    return a;
}

#define CP_ASYNC16(dst, src) \
    asm volatile("cp.async.cg.shared.global [%0], [%1], 16;" \
                 :: "r"(dst), "l"(src) : "memory")
#define CP_COMMIT() asm volatile("cp.async.commit_group;" ::: "memory")
#define CP_WAIT(n)  asm volatile("cp.async.wait_group %0;" :: "n"(n) : "memory")

// ---------------------------------------------------------------------------
// Prep kernels
// ---------------------------------------------------------------------------
__global__ void round_tf32_kernel(const float* __restrict__ src,
                                  float* __restrict__ dst, int n4)
{
    int i = blockIdx.x * blockDim.x + threadIdx.x;
    if (i >= n4) return;
    float4 v = ((const float4*)src)[i];
    ((float4*)dst)[i] = make_float4(f2tf_f(v.x), f2tf_f(v.y), f2tf_f(v.z), f2tf_f(v.w));
}

// dst[C][R] = round(src[R][C]^T)
__global__ void transpose_round_kernel(const float* __restrict__ src,
                                       float* __restrict__ dst, int R, int C)
{
    __shared__ float t[32][33];
    const int bx = blockIdx.x * 32;
    const int by = blockIdx.y * 32;
    const int x = threadIdx.x, y = threadIdx.y;
#pragma unroll
    for (int j = y; j < 32; j += 8)
        t[j][x] = src[(size_t)(by + j) * C + bx + x];
    __syncthreads();
#pragma unroll
    for (int j = y; j < 32; j += 8)
        dst[(size_t)(bx + j) * R + by + x] = f2tf_f(t[x][j]);
}

// ---------------------------------------------------------------------------
// TF32 GEMM v2: C = A[M,K] @ Bt[N,K]^T + bias.
// 128 threads, 4 warps of 64x64. 3-stage cp.async pipeline, BK=16.
// Inputs pre-rounded to tf32 (raw byte moves in the hot loop).
// SPLIT3: N==3072, route output per 1024-col segment to C0/C1/C2 (ldc=1024),
//         outputs tf32-rounded; C0 (q) additionally scaled by 0.125.
// ---------------------------------------------------------------------------
#define GSTR 20                 // padded row stride (floats): banks 20g+tg distinct
#define GTILE (128 * GSTR)      // 2560 floats per matrix per stage
#define GEMM_SMEM (3 * 2 * GTILE * 4)   // 61440 bytes

template<bool SPLIT3>
__global__ __launch_bounds__(128, 2)
void gemm_tc2_kernel(const float* __restrict__ A,
                     const float* __restrict__ Bt,
                     const float* __restrict__ bias,
                     float* __restrict__ C0,
                     float* __restrict__ C1,
                     float* __restrict__ C2,
                     int M, int N, int K)
{
    extern __shared__ float sm[];
    const int tid  = threadIdx.x;
    const int warp = tid >> 5;
    const int lane = tid & 31;
    const int g    = lane >> 2;
    const int tg   = lane & 3;
    const int row0 = blockIdx.y * 128;
    const int col0 = blockIdx.x * 128;
    const int wm   = (warp >> 1) * 64;
    const int wn   = (warp & 1) * 64;

    // per-thread load slots: 4 A chunks + 4 B chunks (16B each)
    const int lr = tid >> 2;            // row 0..31 base (x4 via p)
    const int lc = (tid & 3) * 4;       // chunk col (floats)

    auto issue = [&](int kt, int s) {
        const int k0 = kt * 16;
        float* As = &sm[s * 2 * GTILE];
        float* Bs = As + GTILE;
#pragma unroll
        for (int p = 0; p < 4; p++) {
            const int r = lr + p * 32;
            CP_ASYNC16(smem_u32(&As[r * GSTR + lc]),
                       &A[(size_t)(row0 + r) * K + k0 + lc]);
            CP_ASYNC16(smem_u32(&Bs[r * GSTR + lc]),
                       &Bt[(size_t)(col0 + r) * K + k0 + lc]);
        }
    };

    float acc[4][8][4];
#pragma unroll
    for (int mt = 0; mt < 4; mt++)
#pragma unroll
        for (int nt = 0; nt < 8; nt++)
#pragma unroll
            for (int i = 0; i < 4; i++) acc[mt][nt][i] = 0.0f;

    const int ksteps = K / 16;
    issue(0, 0); CP_COMMIT();
    issue(1, 1); CP_COMMIT();

    for (int kt = 0; kt < ksteps; kt++) {
        const int s = kt % 3;
        if (kt + 1 < ksteps) { CP_WAIT(1); } else { CP_WAIT(0); }
        __syncthreads();
        if (kt + 2 < ksteps) { issue(kt + 2, (kt + 2) % 3); CP_COMMIT(); }

        const unsigned* As = (const unsigned*)&sm[s * 2 * GTILE];
        const unsigned* Bs = As + GTILE;
#pragma unroll
        for (int ks = 0; ks < 2; ks++) {
            unsigned af[4][4], bf[8][2];
#pragma unroll
            for (int mt = 0; mt < 4; mt++) {
                const int r = wm + mt * 16 + g;
                const int c = ks * 8 + tg;
                af[mt][0] = As[r * GSTR + c];
                af[mt][1] = As[(r + 8) * GSTR + c];
                af[mt][2] = As[r * GSTR + c + 4];
                af[mt][3] = As[(r + 8) * GSTR + c + 4];
            }
#pragma unroll
            for (int nt = 0; nt < 8; nt++) {
                const int r = wn + nt * 8 + g;
                const int c = ks * 8 + tg;
                bf[nt][0] = Bs[r * GSTR + c];
                bf[nt][1] = Bs[r * GSTR + c + 4];
            }
#pragma unroll
            for (int mt = 0; mt < 4; mt++)
#pragma unroll
                for (int nt = 0; nt < 8; nt++)
                    mma_tf32(acc[mt][nt], af[mt], bf[nt]);
        }
        __syncthreads();   // before stage s is re-issued at kt+1's issue(kt+3)
    }

    // epilogue
    float* Cout;
    int ccol0, ldc;
    bool is_q = false;
    if (SPLIT3) {
        ldc = EE;
        if (col0 < EE)          { Cout = C0; ccol0 = col0;          is_q = true; }
        else if (col0 < 2 * EE) { Cout = C1; ccol0 = col0 - EE; }
        else                    { Cout = C2; ccol0 = col0 - 2 * EE; }
    } else {
        Cout = C0; ccol0 = col0; ldc = N;
    }

#pragma unroll
    for (int mt = 0; mt < 4; mt++) {
        const int r0 = row0 + wm + mt * 16 + g;
#pragma unroll
        for (int nt = 0; nt < 8; nt++) {
            const int cg = col0 + wn + nt * 8 + 2 * tg;
            const int cs = ccol0 + wn + nt * 8 + 2 * tg;
            float2 bz = *(const float2*)&bias[cg];
            float v00 = acc[mt][nt][0] + bz.x, v01 = acc[mt][nt][1] + bz.y;
            float v10 = acc[mt][nt][2] + bz.x, v11 = acc[mt][nt][3] + bz.y;
            if (SPLIT3) {
                v00 = f2tf_f(v00); v01 = f2tf_f(v01);
                v10 = f2tf_f(v10); v11 = f2tf_f(v11);
                if (is_q) { v00 *= 0.125f; v01 *= 0.125f; v10 *= 0.125f; v11 *= 0.125f; }
            }
            *(float2*)&Cout[(size_t)r0 * ldc + cs]       = make_float2(v00, v01);
            *(float2*)&Cout[(size_t)(r0 + 8) * ldc + cs] = make_float2(v10, v11);
        }
    }
}

// ---------------------------------------------------------------------------
// Flash attention v2: tf32 mma.sync, cp.async K/V double buffering.
// 256 threads (8 warps x 16 q-rows), q-tile 128, k-tile 64.
// Inputs pre-rounded (q also pre-scaled).
// smem (floats): K[2][64*68] | V[2][64*72] | PQ[128*68]
// ---------------------------------------------------------------------------
#define AK_STR 68
#define AV_STR 72
#define AP_STR 68
#define KBUFSZ (64 * AK_STR)          // 4352
#define VBUFSZ (64 * AV_STR)          // 4608
#define SM_K 0
#define SM_V (2 * KBUFSZ)             // 8704
#define SM_P (SM_V + 2 * VBUFSZ)      // 17920
#define ATTN_SMEM ((SM_P + 128 * AP_STR) * 4)   // 106496 bytes

__global__ __launch_bounds__(256, 2)
void flash_attn_tf32_kernel(const float* __restrict__ qsrc,
                            const float* __restrict__ ksrc,
                            const float* __restrict__ vsrc,
                            const float* __restrict__ bias,
                            float* __restrict__ ctx)
{
    extern __shared__ float sm[];
    unsigned* smu = (unsigned*)sm;

    const int qb   = gridDim.x - 1 - blockIdx.x;   // largest tiles first
    const int h    = blockIdx.y;
    const int b    = blockIdx.z;
    const int tid  = threadIdx.x;
    const int warp = tid >> 5;
    const int lane = tid & 31;
    const int g    = lane >> 2;
    const int tg   = lane & 3;
    const int w16  = warp * 16;

    const int tok0 = b * SS;

    // per-thread cp.async slots: row = id>>4, chunk col = (id&15)*4
    const int ar = tid >> 4;            // 0..15 base
    const int ac = (tid & 15) * 4;

    auto issue_kv = [&](int kb, int buf) {
#pragma unroll
        for (int p = 0; p < 4; p++) {
            const int r = ar + p * 16;
            const size_t gi = (size_t)(tok0 + kb * 64 + r) * EE + h * DH + ac;
            CP_ASYNC16(smem_u32(&sm[SM_K + buf * KBUFSZ + r * AK_STR + ac]), &ksrc[gi]);
            CP_ASYNC16(smem_u32(&sm[SM_V + buf * VBUFSZ + r * AV_STR + ac]), &vsrc[gi]);
        }
    };

    // prologue: Q tile + KV tile 0 as group 0
#pragma unroll
    for (int p = 0; p < 8; p++) {
        const int r = ar + p * 16;
        CP_ASYNC16(smem_u32(&sm[SM_P + r * AP_STR + ac]),
                   &qsrc[(size_t)(tok0 + qb * 128 + r) * EE + h * DH + ac]);
    }
    issue_kv(0, 0);
    CP_COMMIT();

    unsigned qa[8][4];
    float m0 = -1e30f, m1 = -1e30f, l0 = 0.0f, l1 = 0.0f;
    float out[8][4];
#pragma unroll
    for (int nt = 0; nt < 8; nt++)
#pragma unroll
        for (int i = 0; i < 4; i++) out[nt][i] = 0.0f;

    const int qg0 = qb * 128 + w16 + g;
    const int qg1 = qg0 + 8;
    const int nkb = 2 * qb + 2;

    for (int kb = 0; kb < nkb; kb++) {
        const int buf = kb & 1;
        if (kb + 1 < nkb) { issue_kv(kb + 1, (kb + 1) & 1); CP_COMMIT(); CP_WAIT(1); }
        else              { CP_WAIT(0); }
        __syncthreads();

        if (kb == 0) {
            // load Q fragments (each warp reads only its own 16-row band)
#pragma unroll
            for (int ks = 0; ks < 8; ks++) {
                const int r = w16 + g;
                qa[ks][0] = smu[SM_P + r * AP_STR + ks * 8 + tg];
                qa[ks][1] = smu[SM_P + (r + 8) * AP_STR + ks * 8 + tg];
                qa[ks][2] = smu[SM_P + r * AP_STR + ks * 8 + tg + 4];
                qa[ks][3] = smu[SM_P + (r + 8) * AP_STR + ks * 8 + tg + 4];
            }
        }

        const unsigned* Ks = &smu[SM_K + buf * KBUFSZ];
        const unsigned* Vs = &smu[SM_V + buf * VBUFSZ];

        // S = Q K^T (16x64 per warp)
        float s[8][4];
#pragma unroll
        for (int nt = 0; nt < 8; nt++) {
#pragma unroll
            for (int i = 0; i < 4; i++) s[nt][i] = 0.0f;
#pragma unroll
            for (int ks = 0; ks < 8; ks++) {
                unsigned bf[2];
                bf[0] = Ks[(nt * 8 + g) * AK_STR + ks * 8 + tg];
                bf[1] = Ks[(nt * 8 + g) * AK_STR + ks * 8 + tg + 4];
                mma_tf32(s[nt], qa[ks], bf);
            }
        }

        // bias + causal mask
        const bool need_mask = (kb * 64 + 63) > qg0;
#pragma unroll
        for (int nt = 0; nt < 8; nt++) {
            const int kg = kb * 64 + nt * 8 + 2 * tg;
            float2 bz0 = *(const float2*)&bias[(size_t)qg0 * SS + kg];
            float2 bz1 = *(const float2*)&bias[(size_t)qg1 * SS + kg];
            s[nt][0] += bz0.x; s[nt][1] += bz0.y;
            s[nt][2] += bz1.x; s[nt][3] += bz1.y;
            if (need_mask) {
                if (kg     > qg0) s[nt][0] = -1e9f;
                if (kg + 1 > qg0) s[nt][1] = -1e9f;
                if (kg     > qg1) s[nt][2] = -1e9f;
                if (kg + 1 > qg1) s[nt][3] = -1e9f;
            }
        }

        // online softmax
        float mx0 = -1e30f, mx1 = -1e30f;
#pragma unroll
        for (int nt = 0; nt < 8; nt++) {
            mx0 = fmaxf(mx0, fmaxf(s[nt][0], s[nt][1]));
            mx1 = fmaxf(mx1, fmaxf(s[nt][2], s[nt][3]));
        }
        mx0 = fmaxf(mx0, __shfl_xor_sync(0xffffffffu, mx0, 1));
        mx0 = fmaxf(mx0, __shfl_xor_sync(0xffffffffu, mx0, 2));
        mx1 = fmaxf(mx1, __shfl_xor_sync(0xffffffffu, mx1, 1));
        mx1 = fmaxf(mx1, __shfl_xor_sync(0xffffffffu, mx1, 2));
        float mn0 = fmaxf(m0, mx0), mn1 = fmaxf(m1, mx1);
        float c0 = __expf(m0 - mn0), c1 = __expf(m1 - mn1);
        m0 = mn0; m1 = mn1;

        float rs0 = 0.0f, rs1 = 0.0f;
#pragma unroll
        for (int nt = 0; nt < 8; nt++) {
            s[nt][0] = __expf(s[nt][0] - mn0);
            s[nt][1] = __expf(s[nt][1] - mn0);
            s[nt][2] = __expf(s[nt][2] - mn1);
            s[nt][3] = __expf(s[nt][3] - mn1);
            rs0 += s[nt][0] + s[nt][1];
            rs1 += s[nt][2] + s[nt][3];
        }
        rs0 += __shfl_xor_sync(0xffffffffu, rs0, 1);
        rs0 += __shfl_xor_sync(0xffffffffu, rs0, 2);
        rs1 += __shfl_xor_sync(0xffffffffu, rs1, 1);
        rs1 += __shfl_xor_sync(0xffffffffu, rs1, 2);
        l0 = l0 * c0 + rs0;
        l1 = l1 * c1 + rs1;
#pragma unroll
        for (int nt = 0; nt < 8; nt++) {
            out[nt][0] *= c0; out[nt][1] *= c0;
            out[nt][2] *= c1; out[nt][3] *= c1;
        }

        // P -> smem (warp-private rows), tf32-rounded
#pragma unroll
        for (int nt = 0; nt < 8; nt++) {
            *(uint2*)&smu[SM_P + (w16 + g) * AP_STR + nt * 8 + 2 * tg] =
                make_uint2(f2tf(s[nt][0]), f2tf(s[nt][1]));
            *(uint2*)&smu[SM_P + (w16 + g + 8) * AP_STR + nt * 8 + 2 * tg] =
                make_uint2(f2tf(s[nt][2]), f2tf(s[nt][3]));
        }
        __syncwarp();

        // out += P V
#pragma unroll
        for (int ks = 0; ks < 8; ks++) {
            unsigned pa[4];
            pa[0] = smu[SM_P + (w16 + g) * AP_STR + ks * 8 + tg];
            pa[1] = smu[SM_P + (w16 + g + 8) * AP_STR + ks * 8 + tg];
            pa[2] = smu[SM_P + (w16 + g) * AP_STR + ks * 8 + tg + 4];
            pa[3] = smu[SM_P + (w16 + g + 8) * AP_STR + ks * 8 + tg + 4];
#pragma unroll
            for (int nt = 0; nt < 8; nt++) {
                unsigned vf[2];
                vf[0] = Vs[(ks * 8 + tg) * AV_STR + nt * 8 + g];
                vf[1] = Vs[(ks * 8 + tg + 4) * AV_STR + nt * 8 + g];
                mma_tf32(out[nt], pa, vf);
            }
        }
        __syncthreads();   // all warps done with buf before it is re-issued
    }

    // write ctx tf32-rounded (feeds proj GEMM raw)
    const float il0 = 1.0f / l0, il1 = 1.0f / l1;
    const int trow = tok0 + qb * 128 + w16 + g;
#pragma unroll
    for (int nt = 0; nt < 8; nt++) {
        const int c = h * DH + nt * 8 + 2 * tg;
        *(float2*)&ctx[(size_t)trow * EE + c] =
            make_float2(f2tf_f(out[nt][0] * il0), f2tf_f(out[nt][1] * il0));
        *(float2*)&ctx[(size_t)(trow + 8) * EE + c] =
            make_float2(f2tf_f(out[nt][2] * il1), f2tf_f(out[nt][3] * il1));
    }
}

// ---------------------------------------------------------------------------
// kernel_launch
// ---------------------------------------------------------------------------
extern "C" void kernel_launch(void* const* d_in, const int* in_sizes, int n_in,
                              void* d_out, int out_size)
{
    const float* hidden = (const float*)d_in[0];
    const float* bias   = (const float*)d_in[1];
    const float* Wqkv   = (const float*)d_in[2];
    const float* bqkv   = (const float*)d_in[3];
    const float* Wproj  = (const float*)d_in[4];
    const float* bproj  = (const float*)d_in[5];
    float* out = (float*)d_out;

    float *qbuf, *ctx, *abuf, *wqkv_t, *wproj_t;
    cudaGetSymbolAddress((void**)&qbuf, g_q);
    cudaGetSymbolAddress((void**)&ctx, g_ctx);
    cudaGetSymbolAddress((void**)&abuf, g_a);
    cudaGetSymbolAddress((void**)&wqkv_t, g_wqkv_t);
    cudaGetSymbolAddress((void**)&wproj_t, g_wproj_t);

    float* out_attn = out;
    float* out_key  = out + (size_t)M_TOK * EE;
    float* out_val  = out + (size_t)2 * M_TOK * EE;

    cudaFuncSetAttribute(flash_attn_tf32_kernel,
                         cudaFuncAttributeMaxDynamicSharedMemorySize, ATTN_SMEM);
    cudaFuncSetAttribute(gemm_tc2_kernel<true>,
                         cudaFuncAttributeMaxDynamicSharedMemorySize, GEMM_SMEM);
    cudaFuncSetAttribute(gemm_tc2_kernel<false>,
                         cudaFuncAttributeMaxDynamicSharedMemorySize, GEMM_SMEM);

    // 0) prep: round hidden; transpose+round weights
    round_tf32_kernel<<<(M_TOK * EE / 4 + 255) / 256, 256>>>(hidden, abuf, M_TOK * EE / 4);
    {
        dim3 blk(32, 8);
        transpose_round_kernel<<<dim3(N_QKV / 32, EE / 32), blk>>>(Wqkv, wqkv_t, EE, N_QKV);
        transpose_round_kernel<<<dim3(EE / 32, EE / 32), blk>>>(Wproj, wproj_t, EE, EE);
    }

    // 1) QKV GEMM, fused cache split (q pre-scaled+rounded, k/v rounded)
    {
        dim3 grid(N_QKV / 128, M_TOK / 128);
        gemm_tc2_kernel<true><<<grid, 128, GEMM_SMEM>>>(abuf, wqkv_t, bqkv,
                                                        qbuf, out_key, out_val,
                                                        M_TOK, N_QKV, EE);
    }
    // 2) attention
    {
        dim3 grid(SS / 128, HH, BB);
        flash_attn_tf32_kernel<<<grid, 256, ATTN_SMEM>>>(qbuf, out_key, out_val,
                                                         bias, ctx);
    }
    // 3) projection
    {
        dim3 grid(EE / 128, M_TOK / 128);
        gemm_tc2_kernel<false><<<grid, 128, GEMM_SMEM>>>(ctx, wproj_t, bproj,
                                                         out_attn, nullptr, nullptr,
                                                         M_TOK, EE, EE);
    }
}

// round 6
// speedup vs baseline: 1.2520x; 1.1227x over previous
#include <cuda_runtime.h>
#include <stdint.h>
#include <math.h>

// Problem constants
#define BB 2
#define SS 2048
#define EE 1024
#define HH 16
#define DH 64
#define M_TOK (BB * SS)        // 4096
#define N_QKV (3 * EE)         // 3072

// Scratch (__device__ globals; no allocations allowed)
__device__ float g_q[M_TOK * EE];        // Q pre-scaled + tf32-rounded
__device__ float g_ctx[M_TOK * EE];      // attention output (tf32-rounded)
__device__ float g_a[M_TOK * EE];        // rounded hidden states
__device__ float g_wqkv_t[N_QKV * EE];   // Wqkv^T rounded [3072,1024]
__device__ float g_wproj_t[EE * EE];     // Wproj^T rounded [1024,1024]

// ---------------------------------------------------------------------------
// helpers
// ---------------------------------------------------------------------------
__device__ __forceinline__ unsigned f2tf(float x) {
    unsigned r;
    asm("cvt.rna.tf32.f32 %0, %1;" : "=r"(r) : "f"(x));
    return r;
}
__device__ __forceinline__ float f2tf_f(float x) { return __uint_as_float(f2tf(x)); }

__device__ __forceinline__ void mma_tf32(float c[4], const unsigned a[4], const unsigned b[2]) {
    asm volatile(
        "mma.sync.aligned.m16n8k8.row.col.f32.tf32.tf32.f32 "
        "{%0,%1,%2,%3}, {%4,%5,%6,%7}, {%8,%9}, {%0,%1,%2,%3};"
        : "+f"(c[0]), "+f"(c[1]), "+f"(c[2]), "+f"(c[3])
        : "r"(a[0]), "r"(a[1]), "r"(a[2]), "r"(a[3]), "r"(b[0]), "r"(b[1]));
}

__device__ __forceinline__ uint32_t smem_u32(const void* p) {
    uint32_t a;
    asm("{ .reg .u64 t; cvta.to.shared.u64 t, %1; cvt.u32.u64 %0, t; }"
        : "=r"(a) : "l"(p));
    return a;
}

#define CP_ASYNC16(dst, src) \
    asm volatile("cp.async.cg.shared.global [%0], [%1], 16;" \
                 :: "r"(dst), "l"(src) : "memory")
#define CP_COMMIT() asm volatile("cp.async.commit_group;" ::: "memory")
#define CP_WAIT(n)  asm volatile("cp.async.wait_group %0;" :: "n"(n) : "memory")

// ---------------------------------------------------------------------------
// Prep kernels
// ---------------------------------------------------------------------------
__global__ void round_tf32_kernel(const float* __restrict__ src,
                                  float* __restrict__ dst, int n4)
{
    int i = blockIdx.x * blockDim.x + threadIdx.x;
    if (i >= n4) return;
    float4 v = ((const float4*)src)[i];
    ((float4*)dst)[i] = make_float4(f2tf_f(v.x), f2tf_f(v.y), f2tf_f(v.z), f2tf_f(v.w));
}

// dst[C][R] = round(src[R][C]^T)
__global__ void transpose_round_kernel(const float* __restrict__ src,
                                       float* __restrict__ dst, int R, int C)
{
    __shared__ float t[32][33];
    const int bx = blockIdx.x * 32;
    const int by = blockIdx.y * 32;
    const int x = threadIdx.x, y = threadIdx.y;
#pragma unroll
    for (int j = y; j < 32; j += 8)
        t[j][x] = src[(size_t)(by + j) * C + bx + x];
    __syncthreads();
#pragma unroll
    for (int j = y; j < 32; j += 8)
        dst[(size_t)(bx + j) * R + by + x] = f2tf_f(t[x][j]);
}

// ---------------------------------------------------------------------------
// TF32 GEMM v2 (unchanged from round 5): C = A[M,K] @ Bt[N,K]^T + bias.
// ---------------------------------------------------------------------------
#define GSTR 20
#define GTILE (128 * GSTR)
#define GEMM_SMEM (3 * 2 * GTILE * 4)   // 61440 bytes

template<bool SPLIT3>
__global__ __launch_bounds__(128, 2)
void gemm_tc2_kernel(const float* __restrict__ A,
                     const float* __restrict__ Bt,
                     const float* __restrict__ bias,
                     float* __restrict__ C0,
                     float* __restrict__ C1,
                     float* __restrict__ C2,
                     int M, int N, int K)
{
    extern __shared__ float sm[];
    const int tid  = threadIdx.x;
    const int warp = tid >> 5;
    const int lane = tid & 31;
    const int g    = lane >> 2;
    const int tg   = lane & 3;
    const int row0 = blockIdx.y * 128;
    const int col0 = blockIdx.x * 128;
    const int wm   = (warp >> 1) * 64;
    const int wn   = (warp & 1) * 64;

    const int lr = tid >> 2;
    const int lc = (tid & 3) * 4;

    auto issue = [&](int kt, int s) {
        const int k0 = kt * 16;
        float* As = &sm[s * 2 * GTILE];
        float* Bs = As + GTILE;
#pragma unroll
        for (int p = 0; p < 4; p++) {
            const int r = lr + p * 32;
            CP_ASYNC16(smem_u32(&As[r * GSTR + lc]),
                       &A[(size_t)(row0 + r) * K + k0 + lc]);
            CP_ASYNC16(smem_u32(&Bs[r * GSTR + lc]),
                       &Bt[(size_t)(col0 + r) * K + k0 + lc]);
        }
    };

    float acc[4][8][4];
#pragma unroll
    for (int mt = 0; mt < 4; mt++)
#pragma unroll
        for (int nt = 0; nt < 8; nt++)
#pragma unroll
            for (int i = 0; i < 4; i++) acc[mt][nt][i] = 0.0f;

    const int ksteps = K / 16;
    issue(0, 0); CP_COMMIT();
    issue(1, 1); CP_COMMIT();

    for (int kt = 0; kt < ksteps; kt++) {
        const int s = kt % 3;
        if (kt + 1 < ksteps) { CP_WAIT(1); } else { CP_WAIT(0); }
        __syncthreads();
        if (kt + 2 < ksteps) { issue(kt + 2, (kt + 2) % 3); CP_COMMIT(); }

        const unsigned* As = (const unsigned*)&sm[s * 2 * GTILE];
        const unsigned* Bs = As + GTILE;
#pragma unroll
        for (int ks = 0; ks < 2; ks++) {
            unsigned af[4][4], bf[8][2];
#pragma unroll
            for (int mt = 0; mt < 4; mt++) {
                const int r = wm + mt * 16 + g;
                const int c = ks * 8 + tg;
                af[mt][0] = As[r * GSTR + c];
                af[mt][1] = As[(r + 8) * GSTR + c];
                af[mt][2] = As[r * GSTR + c + 4];
                af[mt][3] = As[(r + 8) * GSTR + c + 4];
            }
#pragma unroll
            for (int nt = 0; nt < 8; nt++) {
                const int r = wn + nt * 8 + g;
                const int c = ks * 8 + tg;
                bf[nt][0] = Bs[r * GSTR + c];
                bf[nt][1] = Bs[r * GSTR + c + 4];
            }
#pragma unroll
            for (int mt = 0; mt < 4; mt++)
#pragma unroll
                for (int nt = 0; nt < 8; nt++)
                    mma_tf32(acc[mt][nt], af[mt], bf[nt]);
        }
        __syncthreads();
    }

    float* Cout;
    int ccol0, ldc;
    bool is_q = false;
    if (SPLIT3) {
        ldc = EE;
        if (col0 < EE)          { Cout = C0; ccol0 = col0;          is_q = true; }
        else if (col0 < 2 * EE) { Cout = C1; ccol0 = col0 - EE; }
        else                    { Cout = C2; ccol0 = col0 - 2 * EE; }
    } else {
        Cout = C0; ccol0 = col0; ldc = N;
    }

#pragma unroll
    for (int mt = 0; mt < 4; mt++) {
        const int r0 = row0 + wm + mt * 16 + g;
#pragma unroll
        for (int nt = 0; nt < 8; nt++) {
            const int cg = col0 + wn + nt * 8 + 2 * tg;
            const int cs = ccol0 + wn + nt * 8 + 2 * tg;
            float2 bz = *(const float2*)&bias[cg];
            float v00 = acc[mt][nt][0] + bz.x, v01 = acc[mt][nt][1] + bz.y;
            float v10 = acc[mt][nt][2] + bz.x, v11 = acc[mt][nt][3] + bz.y;
            if (SPLIT3) {
                v00 = f2tf_f(v00); v01 = f2tf_f(v01);
                v10 = f2tf_f(v10); v11 = f2tf_f(v11);
                if (is_q) { v00 *= 0.125f; v01 *= 0.125f; v10 *= 0.125f; v11 *= 0.125f; }
            }
            *(float2*)&Cout[(size_t)r0 * ldc + cs]       = make_float2(v00, v01);
            *(float2*)&Cout[(size_t)(r0 + 8) * ldc + cs] = make_float2(v10, v11);
        }
    }
}

// ---------------------------------------------------------------------------
// Flash attention v3: fixed-constant softmax (C=16), 128 threads (4 warps),
// each warp 32 q-rows (mt=2), q-tile 128, k-tile 64, cp.async double buffer.
// smem (floats): K[2][64*68] | V[2][64*72] | QP[128*68]
// ---------------------------------------------------------------------------
#define AK_STR 68
#define AV_STR 72
#define AP_STR 68
#define KBUFSZ (64 * AK_STR)
#define VBUFSZ (64 * AV_STR)
#define SM_K 0
#define SM_V (2 * KBUFSZ)
#define SM_P (SM_V + 2 * VBUFSZ)
#define ATTN_SMEM ((SM_P + 128 * AP_STR) * 4)   // 106496 bytes... (floats*4)
#define SOFTMAX_C 16.0f

__global__ __launch_bounds__(128, 2)
void flash_attn_tf32_kernel(const float* __restrict__ qsrc,
                            const float* __restrict__ ksrc,
                            const float* __restrict__ vsrc,
                            const float* __restrict__ bias,
                            float* __restrict__ ctx)
{
    extern __shared__ float sm[];
    unsigned* smu = (unsigned*)sm;

    const int qb   = gridDim.x - 1 - blockIdx.x;   // largest tiles first
    const int h    = blockIdx.y;
    const int b    = blockIdx.z;
    const int tid  = threadIdx.x;
    const int warp = tid >> 5;
    const int lane = tid & 31;
    const int g    = lane >> 2;
    const int tg   = lane & 3;
    const int w32  = warp * 32;

    const int tok0 = b * SS;

    // cp.async slots: row = tid>>4 (0..7), chunk col = (tid&15)*4
    const int ar = tid >> 4;
    const int ac = (tid & 15) * 4;

    auto issue_kv = [&](int kb, int buf) {
#pragma unroll
        for (int p = 0; p < 8; p++) {
            const int r = ar + p * 8;
            const size_t gi = (size_t)(tok0 + kb * 64 + r) * EE + h * DH + ac;
            CP_ASYNC16(smem_u32(&sm[SM_K + buf * KBUFSZ + r * AK_STR + ac]), &ksrc[gi]);
            CP_ASYNC16(smem_u32(&sm[SM_V + buf * VBUFSZ + r * AV_STR + ac]), &vsrc[gi]);
        }
    };

    // prologue: Q tile (128x64) + KV tile 0 in group 0
#pragma unroll
    for (int p = 0; p < 16; p++) {
        const int r = ar + p * 8;
        CP_ASYNC16(smem_u32(&sm[SM_P + r * AP_STR + ac]),
                   &qsrc[(size_t)(tok0 + qb * 128 + r) * EE + h * DH + ac]);
    }
    issue_kv(0, 0);
    CP_COMMIT();

    unsigned qa[8][2][4];           // [ks][mt][frag]
    float out[2][8][4];
    float rs[2][2];                 // row sums: [mt][row g / g+8]
#pragma unroll
    for (int mt = 0; mt < 2; mt++) {
        rs[mt][0] = 0.0f; rs[mt][1] = 0.0f;
#pragma unroll
        for (int nt = 0; nt < 8; nt++)
#pragma unroll
            for (int i = 0; i < 4; i++) out[mt][nt][i] = 0.0f;
    }

    int qg[2][2];
#pragma unroll
    for (int mt = 0; mt < 2; mt++) {
        qg[mt][0] = qb * 128 + w32 + mt * 16 + g;
        qg[mt][1] = qg[mt][0] + 8;
    }
    const int nkb = 2 * qb + 2;

    for (int kb = 0; kb < nkb; kb++) {
        const int buf = kb & 1;
        if (kb + 1 < nkb) { issue_kv(kb + 1, (kb + 1) & 1); CP_COMMIT(); CP_WAIT(1); }
        else              { CP_WAIT(0); }
        __syncthreads();

        if (kb == 0) {
            // Q fragments to registers (own 32-row band); Q region becomes P
#pragma unroll
            for (int ks = 0; ks < 8; ks++)
#pragma unroll
                for (int mt = 0; mt < 2; mt++) {
                    const int r = w32 + mt * 16 + g;
                    qa[ks][mt][0] = smu[SM_P + r * AP_STR + ks * 8 + tg];
                    qa[ks][mt][1] = smu[SM_P + (r + 8) * AP_STR + ks * 8 + tg];
                    qa[ks][mt][2] = smu[SM_P + r * AP_STR + ks * 8 + tg + 4];
                    qa[ks][mt][3] = smu[SM_P + (r + 8) * AP_STR + ks * 8 + tg + 4];
                }
            __syncthreads();
        }

        const unsigned* Ks = &smu[SM_K + buf * KBUFSZ];
        const unsigned* Vs = &smu[SM_V + buf * VBUFSZ];

        // S = Q K^T  (32x64 per warp; bf shared across mt)
        float s[2][8][4];
#pragma unroll
        for (int mt = 0; mt < 2; mt++)
#pragma unroll
            for (int nt = 0; nt < 8; nt++)
#pragma unroll
                for (int i = 0; i < 4; i++) s[mt][nt][i] = 0.0f;
#pragma unroll
        for (int ks = 0; ks < 8; ks++) {
#pragma unroll
            for (int nt = 0; nt < 8; nt++) {
                unsigned bf[2];
                bf[0] = Ks[(nt * 8 + g) * AK_STR + ks * 8 + tg];
                bf[1] = Ks[(nt * 8 + g) * AK_STR + ks * 8 + tg + 4];
                mma_tf32(s[0][nt], qa[ks][0], bf);
                mma_tf32(s[1][nt], qa[ks][1], bf);
            }
        }

        // bias + causal mask + exp(s - C) + row-sum accumulation + P store
        const bool need_mask = (kb * 64 + 63) > qg[0][0];
#pragma unroll
        for (int mt = 0; mt < 2; mt++) {
#pragma unroll
            for (int nt = 0; nt < 8; nt++) {
                const int kg = kb * 64 + nt * 8 + 2 * tg;
                float2 bz0 = *(const float2*)&bias[(size_t)qg[mt][0] * SS + kg];
                float2 bz1 = *(const float2*)&bias[(size_t)qg[mt][1] * SS + kg];
                float v0 = s[mt][nt][0] + bz0.x - SOFTMAX_C;
                float v1 = s[mt][nt][1] + bz0.y - SOFTMAX_C;
                float v2 = s[mt][nt][2] + bz1.x - SOFTMAX_C;
                float v3 = s[mt][nt][3] + bz1.y - SOFTMAX_C;
                if (need_mask) {
                    if (kg     > qg[mt][0]) v0 = -1e9f;
                    if (kg + 1 > qg[mt][0]) v1 = -1e9f;
                    if (kg     > qg[mt][1]) v2 = -1e9f;
                    if (kg + 1 > qg[mt][1]) v3 = -1e9f;
                }
                float p0 = __expf(v0), p1 = __expf(v1);
                float p2 = __expf(v2), p3 = __expf(v3);
                rs[mt][0] += p0 + p1;
                rs[mt][1] += p2 + p3;
                const int r = w32 + mt * 16 + g;
                *(uint2*)&smu[SM_P + r * AP_STR + nt * 8 + 2 * tg] =
                    make_uint2(f2tf(p0), f2tf(p1));
                *(uint2*)&smu[SM_P + (r + 8) * AP_STR + nt * 8 + 2 * tg] =
                    make_uint2(f2tf(p2), f2tf(p3));
            }
        }
        __syncwarp();

        // out += P V  (vf shared across mt)
#pragma unroll
        for (int ks = 0; ks < 8; ks++) {
            unsigned pa[2][4];
#pragma unroll
            for (int mt = 0; mt < 2; mt++) {
                const int r = w32 + mt * 16 + g;
                pa[mt][0] = smu[SM_P + r * AP_STR + ks * 8 + tg];
                pa[mt][1] = smu[SM_P + (r + 8) * AP_STR + ks * 8 + tg];
                pa[mt][2] = smu[SM_P + r * AP_STR + ks * 8 + tg + 4];
                pa[mt][3] = smu[SM_P + (r + 8) * AP_STR + ks * 8 + tg + 4];
            }
#pragma unroll
            for (int nt = 0; nt < 8; nt++) {
                unsigned vf[2];
                vf[0] = Vs[(ks * 8 + tg) * AV_STR + nt * 8 + g];
                vf[1] = Vs[(ks * 8 + tg + 4) * AV_STR + nt * 8 + g];
                mma_tf32(out[0][nt], pa[0], vf);
                mma_tf32(out[1][nt], pa[1], vf);
            }
        }
        __syncthreads();   // protect K/V buffer before re-issue
    }

    // final row-sum reduction across the tg quad (lanes sharing a row)
#pragma unroll
    for (int mt = 0; mt < 2; mt++)
#pragma unroll
        for (int j = 0; j < 2; j++) {
            rs[mt][j] += __shfl_xor_sync(0xffffffffu, rs[mt][j], 1);
            rs[mt][j] += __shfl_xor_sync(0xffffffffu, rs[mt][j], 2);
        }

    // write ctx tf32-rounded (feeds proj GEMM raw)
#pragma unroll
    for (int mt = 0; mt < 2; mt++) {
        const float il0 = 1.0f / rs[mt][0], il1 = 1.0f / rs[mt][1];
        const int trow = tok0 + qb * 128 + w32 + mt * 16 + g;
#pragma unroll
        for (int nt = 0; nt < 8; nt++) {
            const int c = h * DH + nt * 8 + 2 * tg;
            *(float2*)&ctx[(size_t)trow * EE + c] =
                make_float2(f2tf_f(out[mt][nt][0] * il0), f2tf_f(out[mt][nt][1] * il0));
            *(float2*)&ctx[(size_t)(trow + 8) * EE + c] =
                make_float2(f2tf_f(out[mt][nt][2] * il1), f2tf_f(out[mt][nt][3] * il1));
        }
    }
}

// ---------------------------------------------------------------------------
// kernel_launch
// ---------------------------------------------------------------------------
extern "C" void kernel_launch(void* const* d_in, const int* in_sizes, int n_in,
                              void* d_out, int out_size)
{
    const float* hidden = (const float*)d_in[0];
    const float* bias   = (const float*)d_in[1];
    const float* Wqkv   = (const float*)d_in[2];
    const float* bqkv   = (const float*)d_in[3];
    const float* Wproj  = (const float*)d_in[4];
    const float* bproj  = (const float*)d_in[5];
    float* out = (float*)d_out;

    float *qbuf, *ctx, *abuf, *wqkv_t, *wproj_t;
    cudaGetSymbolAddress((void**)&qbuf, g_q);
    cudaGetSymbolAddress((void**)&ctx, g_ctx);
    cudaGetSymbolAddress((void**)&abuf, g_a);
    cudaGetSymbolAddress((void**)&wqkv_t, g_wqkv_t);
    cudaGetSymbolAddress((void**)&wproj_t, g_wproj_t);

    float* out_attn = out;
    float* out_key  = out + (size_t)M_TOK * EE;
    float* out_val  = out + (size_t)2 * M_TOK * EE;

    cudaFuncSetAttribute(flash_attn_tf32_kernel,
                         cudaFuncAttributeMaxDynamicSharedMemorySize, ATTN_SMEM);
    cudaFuncSetAttribute(gemm_tc2_kernel<true>,
                         cudaFuncAttributeMaxDynamicSharedMemorySize, GEMM_SMEM);
    cudaFuncSetAttribute(gemm_tc2_kernel<false>,
                         cudaFuncAttributeMaxDynamicSharedMemorySize, GEMM_SMEM);

    // 0) prep: round hidden; transpose+round weights
    round_tf32_kernel<<<(M_TOK * EE / 4 + 255) / 256, 256>>>(hidden, abuf, M_TOK * EE / 4);
    {
        dim3 blk(32, 8);
        transpose_round_kernel<<<dim3(N_QKV / 32, EE / 32), blk>>>(Wqkv, wqkv_t, EE, N_QKV);
        transpose_round_kernel<<<dim3(EE / 32, EE / 32), blk>>>(Wproj, wproj_t, EE, EE);
    }

    // 1) QKV GEMM, fused cache split (q pre-scaled+rounded, k/v rounded)
    {
        dim3 grid(N_QKV / 128, M_TOK / 128);
        gemm_tc2_kernel<true><<<grid, 128, GEMM_SMEM>>>(abuf, wqkv_t, bqkv,
                                                        qbuf, out_key, out_val,
                                                        M_TOK, N_QKV, EE);
    }
    // 2) attention
    {
        dim3 grid(SS / 128, HH, BB);
        flash_attn_tf32_kernel<<<grid, 128, ATTN_SMEM>>>(qbuf, out_key, out_val,
                                                         bias, ctx);
    }
    // 3) projection
    {
        dim3 grid(EE / 128, M_TOK / 128);
        gemm_tc2_kernel<false><<<grid, 128, GEMM_SMEM>>>(ctx, wproj_t, bproj,
                                                         out_attn, nullptr, nullptr,
                                                         M_TOK, EE, EE);
    }
}